// round 16
// baseline (speedup 1.0000x reference)
#include <cuda_runtime.h>
#include <cuda_fp16.h>
#include <cstdint>

// Problem constants: N_UNIQUE=10000, N_BASES=10, FILTERS=16, B=32, L=100000
#define N_UNIQUE 10000
#define N_BASES  10
#define FILTERS  16
#define N_ELEMS  (32 * 100000)            // 3,200,000
#define TPB      1024
#define K_SLOTS  10                        // slots per thread per chunk
#define CHUNK_ELEMS 5120                   // TPB*K_SLOTS/2 (2 slots per element)
#define N_CHUNKS 625                       // 3,200,000 / 5120 exactly
#define N_BSLICES 74
#define GRID     (N_BSLICES * 2)           // 148 blocks: 74 slices x 2 halves
#define TAB_BYTES (N_UNIQUE * 16)          // 160,000 B fp16 half-table
#define IDXBUF_INTS CHUNK_ELEMS            // 5,120 ints = 20,480 B per buffer
#define SMEM_TOTAL (TAB_BYTES + 2 * IDXBUF_INTS * 4)   // 200,960 B

// Half-sharded fp16 table (bias folded in): g_tabh[h][u][c] = filter 8h+c.
__device__ __half g_tabh[2][N_UNIQUE][8];

// Kernel 1: tab = X_spline @ kernel + bias, quantized to fp16, half-major.
__global__ void precompute_shrunk(const float* __restrict__ X_spline,
                                  const float* __restrict__ kern,
                                  const float* __restrict__ bias) {
    int t = blockIdx.x * blockDim.x + threadIdx.x;
    if (t >= N_UNIQUE * FILTERS) return;
    int u = t >> 4;
    int f = t & 15;
    float acc = __ldg(bias + f);
#pragma unroll
    for (int b = 0; b < N_BASES; ++b)
        acc = fmaf(__ldg(X_spline + u * N_BASES + b), __ldg(kern + b * FILTERS + f), acc);
    g_tabh[f >> 3][u][f & 7] = __float2half_rn(acc);
}

// Kernel 2: block (slice, half h) holds the fp16 half-table in SMEM; idx is
// streamed ahead via double-buffered cp.async. Inner loop is smem-only plus
// fire-and-forget streaming stores (lane pairs = full 32B sectors).
__global__ __launch_bounds__(TPB, 1) void gather_out(const int* __restrict__ idx,
                                                     float4* __restrict__ out4) {
    extern __shared__ char smem[];
    uint2* tab2 = reinterpret_cast<uint2*>(smem);            // [2*N_UNIQUE] 8B
    int*   ibuf = reinterpret_cast<int*>(smem + TAB_BYTES);  // [2][5120]

    const unsigned tid = threadIdx.x;
    const unsigned h   = blockIdx.x & 1u;
    const unsigned bs  = blockIdx.x >> 1;
    const unsigned c0  = (bs * N_CHUNKS) / N_BSLICES;
    const unsigned c1  = ((bs + 1u) * N_CHUNKS) / N_BSLICES;
    const unsigned j   = tid & 1u;

    // Fill the 160KB half-table (contiguous 16B loads, fully coalesced).
    {
        const uint4* src = reinterpret_cast<const uint4*>(g_tabh[h]);
        uint4* dst = reinterpret_cast<uint4*>(tab2);
        for (unsigned t = tid; t < N_UNIQUE; t += TPB)
            dst[t] = __ldg(src + t);
    }

    // Async idx prefetch of one 5120-int chunk:
    //   all 1024 threads load 16B   -> ints [0, 4096)
    //   threads 0..255 load 16B more -> ints [4096, 5120)
    auto prefetch = [&](unsigned c, int slot) {
        const int* gbase = idx + c * CHUNK_ELEMS;
        int* sbase = ibuf + slot * IDXBUF_INTS;
        {
            unsigned s = (unsigned)__cvta_generic_to_shared(sbase + tid * 4);
            asm volatile("cp.async.cg.shared.global [%0], [%1], 16;"
                         :: "r"(s), "l"(gbase + tid * 4) : "memory");
        }
        if (tid < (IDXBUF_INTS - 4 * TPB) / 4) {   // 256 threads
            unsigned off = 4 * TPB + tid * 4;
            unsigned s = (unsigned)__cvta_generic_to_shared(sbase + off);
            asm volatile("cp.async.cg.shared.global [%0], [%1], 16;"
                         :: "r"(s), "l"(gbase + off) : "memory");
        }
    };

    prefetch(c0, 0);
    asm volatile("cp.async.commit_group;" ::: "memory");
    __syncthreads();                        // table visible to all

    unsigned it = 0;
    for (unsigned c = c0; c < c1; ++c, ++it) {
        const int cur = it & 1;
        if (c + 1 < c1) prefetch(c + 1, cur ^ 1);
        asm volatile("cp.async.commit_group;" ::: "memory");
        asm volatile("cp.async.wait_group 1;" ::: "memory");
        __syncthreads();                    // chunk c idx ready

        const int* myIdx = ibuf + cur * IDXBUF_INTS;
        const unsigned eBase = c * CHUNK_ELEMS;

        // Phase 1: smem idx reads (lane pairs broadcast, conflict-free).
        int u[K_SLOTS];
#pragma unroll
        for (int k = 0; k < K_SLOTS; ++k)
            u[k] = myIdx[(tid + k * TPB) >> 1];

        // Phase 2: random 8B table gathers from SMEM (off the LTS path).
        uint2 hv[K_SLOTS];
#pragma unroll
        for (int k = 0; k < K_SLOTS; ++k)
            hv[k] = tab2[(unsigned)u[k] * 2u + j];

        // Phase 3: cvt fp16->fp32, streaming 16B stores (full 32B sectors
        // per lane pair; element row split only at sector granularity).
#pragma unroll
        for (int k = 0; k < K_SLOTS; ++k) {
            unsigned s = tid + k * TPB;
            unsigned e = eBase + (s >> 1);
            float2 lo = __half22float2(*reinterpret_cast<__half2*>(&hv[k].x));
            float2 hi = __half22float2(*reinterpret_cast<__half2*>(&hv[k].y));
            __stcs(out4 + ((size_t)e * 4u + h * 2u + j),
                   make_float4(lo.x, lo.y, hi.x, hi.y));
        }
        __syncthreads();                    // guard next prefetch overwrite
    }
}

extern "C" void kernel_launch(void* const* d_in, const int* in_sizes, int n_in,
                              void* d_out, int out_size) {
    // Identify inputs by element count (all distinct):
    // idx: 3,200,000 | X_spline: 100,000 | kernel: 160 | bias: 16
    const int*   idx      = nullptr;
    const float* X_spline = nullptr;
    const float* kern     = nullptr;
    const float* bias     = nullptr;
    for (int i = 0; i < n_in; ++i) {
        switch (in_sizes[i]) {
            case N_ELEMS:             idx      = (const int*)  d_in[i]; break;
            case N_UNIQUE * N_BASES:  X_spline = (const float*)d_in[i]; break;
            case N_BASES * FILTERS:   kern     = (const float*)d_in[i]; break;
            case FILTERS:             bias     = (const float*)d_in[i]; break;
            default: break;
        }
    }

    static bool attr_done = false;
    if (!attr_done) {
        cudaFuncSetAttribute(gather_out,
                             cudaFuncAttributeMaxDynamicSharedMemorySize,
                             SMEM_TOTAL);
        attr_done = true;
    }

    {
        int total = N_UNIQUE * FILTERS;
        precompute_shrunk<<<(total + 255) / 256, 256>>>(X_spline, kern, bias);
    }
    gather_out<<<GRID, TPB, SMEM_TOTAL>>>(idx, (float4*)d_out);
}

// round 17
// speedup vs baseline: 1.1059x; 1.1059x over previous
#include <cuda_runtime.h>

// Problem constants: N_UNIQUE=10000, N_BASES=10, FILTERS=16, B=32, L=100000
#define N_UNIQUE 10000
#define N_BASES  10
#define FILTERS  16
#define N_ELEMS  (32 * 100000)           // 3,200,000
#define N_OUT4   (N_ELEMS * 4)           // 12,800,000 float4 outputs
#define UNROLL   4
#define TPB      256
#define GATHER_BLOCKS (N_OUT4 / (TPB * UNROLL))   // 12500 exactly, no tail

// Precomputed bias-fused unique-value table, fp32 (device global scratch).
__device__ float4 g_shrunk4[N_UNIQUE * 4];   // [n_unique][16 floats] as 4x float4

// Kernel 1: shrunk_biased[u][f] = sum_b X_spline[u][b]*kernel[b][f] + bias[f]
__global__ void precompute_shrunk(const float* __restrict__ X_spline,
                                  const float* __restrict__ kern,
                                  const float* __restrict__ bias) {
    int t = blockIdx.x * blockDim.x + threadIdx.x;
    if (t < N_UNIQUE * FILTERS) {
        int u = t >> 4;
        int f = t & 15;
        float acc = __ldg(bias + f);
#pragma unroll
        for (int b = 0; b < N_BASES; ++b)
            acc = fmaf(__ldg(X_spline + u * N_BASES + b),
                       __ldg(kern + b * FILTERS + f), acc);
        reinterpret_cast<float*>(g_shrunk4)[t] = acc;
    }
    // Allow the dependent gather grid to begin launching now; its
    // cudaGridDependencySynchronize() still waits for our completion.
    cudaTriggerProgrammaticLaunchCompletion();
}

// Kernel 2 (PDL secondary): out[e][f] = table[idx[e]][f].
// Proven R2 pattern: slot i -> element e=i>>2, quarter j=i&3; all loads and
// stores fully coalesced. idx loads are issued BEFORE the grid-dependency
// sync (they don't depend on the table), hiding precompute + launch gap.
__global__ __launch_bounds__(TPB) void gather_out(const int* __restrict__ idx,
                                                  float4* __restrict__ out4) {
    const unsigned base = blockIdx.x * (TPB * UNROLL) + threadIdx.x;

    // Phase 1: 4 independent idx loads (streamed), in flight across the sync.
    int u[UNROLL];
#pragma unroll
    for (int k = 0; k < UNROLL; ++k)
        u[k] = __ldcs(idx + ((base + k * TPB) >> 2));

    // Wait for precompute's table writes to be visible.
    cudaGridDependencySynchronize();

    // Phase 2: 4 independent table gathers (L2-resident).
    float4 v[UNROLL];
#pragma unroll
    for (int k = 0; k < UNROLL; ++k) {
        unsigned i = base + k * TPB;
        v[k] = __ldg(&g_shrunk4[(unsigned)u[k] * 4u + (i & 3u)]);
    }

    // Phase 3: 4 streaming stores (write-once, evict-first).
#pragma unroll
    for (int k = 0; k < UNROLL; ++k)
        __stcs(out4 + (base + k * TPB), v[k]);
}

extern "C" void kernel_launch(void* const* d_in, const int* in_sizes, int n_in,
                              void* d_out, int out_size) {
    // Identify inputs by element count (all distinct):
    // idx: 3,200,000 | X_spline: 100,000 | kernel: 160 | bias: 16
    const int*   idx      = nullptr;
    const float* X_spline = nullptr;
    const float* kern     = nullptr;
    const float* bias     = nullptr;
    for (int i = 0; i < n_in; ++i) {
        switch (in_sizes[i]) {
            case N_ELEMS:             idx      = (const int*)  d_in[i]; break;
            case N_UNIQUE * N_BASES:  X_spline = (const float*)d_in[i]; break;
            case N_BASES * FILTERS:   kern     = (const float*)d_in[i]; break;
            case FILTERS:             bias     = (const float*)d_in[i]; break;
            default: break;
        }
    }

    // Primary: plain launch.
    {
        int total = N_UNIQUE * FILTERS;
        precompute_shrunk<<<(total + TPB - 1) / TPB, TPB>>>(X_spline, kern, bias);
    }

    // Secondary: PDL launch — may begin while precompute is still running;
    // the in-kernel cudaGridDependencySynchronize() provides correctness.
    {
        cudaLaunchConfig_t cfg = {};
        cfg.gridDim  = dim3(GATHER_BLOCKS, 1, 1);
        cfg.blockDim = dim3(TPB, 1, 1);
        cfg.dynamicSmemBytes = 0;
        cfg.stream = 0;
        cudaLaunchAttribute attrs[1];
        attrs[0].id = cudaLaunchAttributeProgrammaticStreamSerialization;
        attrs[0].val.programmaticStreamSerializationAllowed = 1;
        cfg.attrs = attrs;
        cfg.numAttrs = 1;
        cudaLaunchKernelEx(&cfg, gather_out, idx, (float4*)d_out);
    }
}